// round 9
// baseline (speedup 1.0000x reference)
#include <cuda_runtime.h>

#define DIM    4096
#define RANK   32
#define NROWS  32          // B(4) * 8 edited rows
#define NDOTS  64          // per row: 32 src + 32 proj
#define NSPLIT 16          // K-dim split per dot

// Partial dot products: [row j][dot di][split]
__device__ float g_part[NROWS * NDOTS * NSPLIT];

// ---------------------------------------------------------------------------
// dots: one warp per (edited row j, dot di, K-split).
// 32*64*16 = 32768 warp-tasks = 4096 CTAs x 8 warps.
// Each warp: 64 float4 (2 per lane, fully unrolled) -> high MLP, latency-bound
// time ~ 2 cold-DRAM round trips instead of 8.
// ---------------------------------------------------------------------------
__global__ __launch_bounds__(256) void dots_kernel(
    const float* __restrict__ hs,
    const float* __restrict__ Wsrc_p, const float* __restrict__ Wproj_p,
    const float* __restrict__ Wsrc_s, const float* __restrict__ Wproj_s,
    const int* __restrict__ offsets, const int* __restrict__ seqlens)
{
    const int warp = threadIdx.x >> 5;
    const int lane = threadIdx.x & 31;
    const int gw = blockIdx.x * 8 + warp;     // 0..32767
    const int j     = gw >> 10;               // 0..31
    const int di    = (gw >> 4) & 63;         // 0..63
    const int split = gw & 15;                // 0..15

    const int b = j >> 3;
    const int slot = j & 7;
    int pos;
    const float *Wsrc, *Wproj;
    if (slot < 4) {
        pos = offsets[b] + slot;
        Wsrc = Wsrc_p; Wproj = Wproj_p;
    } else {
        pos = offsets[b] + seqlens[b] - 8 + slot;
        Wsrc = Wsrc_s; Wproj = Wproj_s;
    }

    const float4* x4 = (const float4*)(hs + ((long)b * 4096 + pos) * DIM);
    const float4* W4 = (const float4*)((di < RANK)
                           ? (Wsrc  + (long)di * DIM)
                           : (Wproj + (long)(di - RANK) * DIM));

    const int k0 = split * (DIM / 4 / NSPLIT);   // 64 float4 per split
    const int i0 = k0 + lane;
    float4 w0 = W4[i0];
    float4 w1 = W4[i0 + 32];
    float4 v0 = x4[i0];
    float4 v1 = x4[i0 + 32];
    float acc = w0.x * v0.x + w0.y * v0.y + w0.z * v0.z + w0.w * v0.w
              + w1.x * v1.x + w1.y * v1.y + w1.z * v1.z + w1.w * v1.w;
    #pragma unroll
    for (int o = 16; o > 0; o >>= 1)
        acc += __shfl_xor_sync(0xffffffff, acc, o);
    if (lane == 0) g_part[(j * NDOTS + di) * NSPLIT + split] = acc;
}

// ---------------------------------------------------------------------------
// copy: R1's exact predicate-free grid-stride float4 copy (~80% DRAM).
// Writes ALL rows (edited rows overwritten by apply afterwards).
// ---------------------------------------------------------------------------
__global__ __launch_bounds__(256) void copy_kernel(const float4* __restrict__ in,
                                                   float4* __restrict__ out,
                                                   long n4) {
    long i = (long)blockIdx.x * blockDim.x + threadIdx.x;
    long stride = (long)gridDim.x * blockDim.x;
    for (; i < n4; i += stride) {
        out[i] = in[i];
    }
}

// ---------------------------------------------------------------------------
// apply: one CTA per edited row; reduces g_part, writes x + s·Wproj.
// Runs after copy: overwrites the plain-copied edited rows.
// ---------------------------------------------------------------------------
__global__ __launch_bounds__(256) void apply_kernel(
    const float* __restrict__ hs,
    const float* __restrict__ bsrc_p, const float* __restrict__ Wproj_p,
    const float* __restrict__ bsrc_s, const float* __restrict__ Wproj_s,
    const int* __restrict__ offsets, const int* __restrict__ seqlens,
    float* __restrict__ out)
{
    const int j = blockIdx.x;              // 0..31
    const int tid = threadIdx.x;
    const int b = j >> 3;
    const int slot = j & 7;
    int pos;
    const float *bias, *Wproj;
    if (slot < 4) {
        pos = offsets[b] + slot;
        bias = bsrc_p; Wproj = Wproj_p;
    } else {
        pos = offsets[b] + seqlens[b] - 8 + slot;
        bias = bsrc_s; Wproj = Wproj_s;
    }

    __shared__ float s[RANK];
    if (tid < RANK) {
        const float* pp = &g_part[(j * NDOTS + tid) * NSPLIT];
        const float* qq = &g_part[(j * NDOTS + RANK + tid) * NSPLIT];
        float src = bias[tid], proj = 0.f;
        #pragma unroll
        for (int k = 0; k < NSPLIT; k++) {
            src  += pp[k];
            proj += qq[k];
        }
        s[tid] = (src > 0.f ? src : 0.f) - proj;
    }
    __syncthreads();

    const long base = ((long)b * 4096 + pos) * DIM;
    const float4* x4 = (const float4*)(hs + base);
    float4*       o4 = (float4*)(out + base);
    #pragma unroll
    for (int k = 0; k < 4; k++) {
        int i = tid + k * 256;
        float4 acc = x4[i];
        #pragma unroll
        for (int r = 0; r < RANK; r++) {
            float4 w = ((const float4*)(Wproj + (long)r * DIM))[i];
            float sr = s[r];
            acc.x += sr * w.x;
            acc.y += sr * w.y;
            acc.z += sr * w.z;
            acc.w += sr * w.w;
        }
        o4[i] = acc;
    }
}

extern "C" void kernel_launch(void* const* d_in, const int* in_sizes, int n_in,
                              void* d_out, int out_size) {
    const float* hs      = (const float*)d_in[0];
    const float* Wsrc_p  = (const float*)d_in[1];
    const float* bsrc_p  = (const float*)d_in[2];
    const float* Wproj_p = (const float*)d_in[3];
    const float* Wsrc_s  = (const float*)d_in[4];
    const float* bsrc_s  = (const float*)d_in[5];
    const float* Wproj_s = (const float*)d_in[6];
    const int*   offsets = (const int*)d_in[7];
    const int*   seqlens = (const int*)d_in[8];
    float* out = (float*)d_out;

    dots_kernel<<<4096, 256>>>(hs, Wsrc_p, Wproj_p, Wsrc_s, Wproj_s,
                               offsets, seqlens);

    const long n4 = (long)out_size / 4;    // float4 count
    copy_kernel<<<8192, 256>>>((const float4*)hs, (float4*)out, n4);

    apply_kernel<<<NROWS, 256>>>(hs, bsrc_p, Wproj_p, bsrc_s, Wproj_s,
                                 offsets, seqlens, out);
}